// round 13
// baseline (speedup 1.0000x reference)
#include <cuda_runtime.h>
#include <cuda_bf16.h>
#include <stdint.h>

#define SQ   2048
#define DM   1024
#define NH   16
#define HDD  64
#define NK   64

// fp32 hidden buffer (attn gathers from this)
__device__ float g_h[SQ * DM];
// bf16 hi/lo operand copies
__device__ __nv_bfloat16 g_xh[SQ * DM], g_xl[SQ * DM];
__device__ __nv_bfloat16 g_wih[DM * DM], g_wil[DM * DM];
__device__ __nv_bfloat16 g_woh[DM * DM], g_wol[DM * DM];
__device__ __nv_bfloat16 g_fh[SQ * DM], g_fl[SQ * DM];

// ---------------------------------------------------------------------------
// Single-launch split of {x, W_in, W_out} into bf16 hi/lo.
// ---------------------------------------------------------------------------
__global__ __launch_bounds__(256)
void cvt_all(const float* __restrict__ x,
             const float* __restrict__ wi,
             const float* __restrict__ wo,
             __nv_bfloat16* __restrict__ xh, __nv_bfloat16* __restrict__ xl,
             __nv_bfloat16* __restrict__ wih, __nv_bfloat16* __restrict__ wil,
             __nv_bfloat16* __restrict__ woh, __nv_bfloat16* __restrict__ wol)
{
    const int i = (blockIdx.x * 256 + threadIdx.x) * 4;
    const float* src;
    __nv_bfloat16 *hi, *lo;
    int off;
    if (i < SQ * DM)              { src = x;  hi = xh;  lo = xl;  off = i; }
    else if (i < SQ * DM + DM*DM) { src = wi; hi = wih; lo = wil; off = i - SQ * DM; }
    else                          { src = wo; hi = woh; lo = wol; off = i - SQ * DM - DM * DM; }

    float4 v = *(const float4*)(src + off);
    __nv_bfloat16 h0 = __float2bfloat16(v.x);
    __nv_bfloat16 h1 = __float2bfloat16(v.y);
    __nv_bfloat16 h2 = __float2bfloat16(v.z);
    __nv_bfloat16 h3 = __float2bfloat16(v.w);
    __nv_bfloat162 hv0; hv0.x = h0; hv0.y = h1;
    __nv_bfloat162 hv1; hv1.x = h2; hv1.y = h3;
    __nv_bfloat162 lv0, lv1;
    lv0.x = __float2bfloat16(v.x - __bfloat162float(h0));
    lv0.y = __float2bfloat16(v.y - __bfloat162float(h1));
    lv1.x = __float2bfloat16(v.z - __bfloat162float(h2));
    lv1.y = __float2bfloat16(v.w - __bfloat162float(h3));
    *(__nv_bfloat162*)(hi + off)     = hv0;
    *(__nv_bfloat162*)(hi + off + 2) = hv1;
    *(__nv_bfloat162*)(lo + off)     = lv0;
    *(__nv_bfloat162*)(lo + off + 2) = lv1;
}

// ---------------------------------------------------------------------------
// bf16x3 NT GEMM (unchanged from R11/R12 best). Tile 128x128xBK32, 256 thr.
// ---------------------------------------------------------------------------
#define SROW 40
#define AELEM (128 * SROW)
#define BUFELEM (4 * AELEM)
#define GSMEM (2 * BUFELEM * 2)

__device__ __forceinline__ void cp16(uint32_t sdst, const void* gsrc) {
    asm volatile("cp.async.cg.shared.global [%0], [%1], 16;" ::
                 "r"(sdst), "l"(gsrc));
}
__device__ __forceinline__ void cp_commit() {
    asm volatile("cp.async.commit_group;");
}
__device__ __forceinline__ void mma_bf16(float* c, const uint32_t* a, const uint32_t* b) {
    asm volatile(
        "mma.sync.aligned.m16n8k16.row.col.f32.bf16.bf16.f32 "
        "{%0,%1,%2,%3}, {%4,%5,%6,%7}, {%8,%9}, {%0,%1,%2,%3};"
        : "+f"(c[0]), "+f"(c[1]), "+f"(c[2]), "+f"(c[3])
        : "r"(a[0]), "r"(a[1]), "r"(a[2]), "r"(a[3]), "r"(b[0]), "r"(b[1]));
}

template <bool EPI>
__global__ __launch_bounds__(256, 1)
void gemm_bf16x3(const __nv_bfloat16* __restrict__ Ah,
                 const __nv_bfloat16* __restrict__ Al,
                 const __nv_bfloat16* __restrict__ Bh,
                 const __nv_bfloat16* __restrict__ Bl,
                 float* __restrict__ C,
                 const float* __restrict__ bias,
                 const float* __restrict__ resid)
{
    constexpr int KD = 1024, NC = 1024, NS = 32;

    extern __shared__ __nv_bfloat16 sm[];
    uint32_t sbase;
    asm("{ .reg .u64 t; cvta.to.shared.u64 t, %1; cvt.u32.u64 %0, t; }"
        : "=r"(sbase) : "l"(sm));

    const int t    = threadIdx.x;
    const int lane = t & 31;
    const int w    = t >> 5;
    const int wm   = w >> 2;
    const int wn   = w & 3;
    const int bm   = blockIdx.y;
    const int bn   = blockIdx.x;
    const int r4   = lane >> 2;
    const int c4   = lane & 3;

    const __nv_bfloat16* gsrc[4] = {
        Ah + (size_t)(bm * 128) * KD, Al + (size_t)(bm * 128) * KD,
        Bh + (size_t)(bn * 128) * KD, Bl + (size_t)(bn * 128) * KD };

    float acc[4][4][4];
#pragma unroll
    for (int i = 0; i < 4; i++)
#pragma unroll
        for (int j = 0; j < 4; j++)
#pragma unroll
            for (int q = 0; q < 4; q++) acc[i][j][q] = 0.f;

    auto issue_stage = [&](int ks, int buf) {
        const int k0 = ks * 32;
#pragma unroll
        for (int arr = 0; arr < 4; arr++) {
            const uint32_t ab = sbase + (uint32_t)(buf * BUFELEM + arr * AELEM) * 2;
            const __nv_bfloat16* src = gsrc[arr];
#pragma unroll
            for (int i = 0; i < 2; i++) {
                const int c = t + i * 256;
                const int row = c >> 2, j = c & 3;
                cp16(ab + (uint32_t)(row * SROW + j * 8) * 2,
                     src + (size_t)row * KD + k0 + j * 8);
            }
        }
        cp_commit();
    };

    issue_stage(0, 0);

    for (int ks = 0; ks < NS; ks++) {
        const int buf = ks & 1;
        if (ks + 1 < NS) {
            issue_stage(ks + 1, buf ^ 1);
            asm volatile("cp.async.wait_group 1;");
        } else {
            asm volatile("cp.async.wait_group 0;");
        }
        __syncthreads();

        const __nv_bfloat16* sAh = sm + buf * BUFELEM;
        const __nv_bfloat16* sAl = sAh + AELEM;
        const __nv_bfloat16* sBh = sAl + AELEM;
        const __nv_bfloat16* sBl = sBh + AELEM;

#pragma unroll
        for (int kk = 0; kk < 2; kk++) {
            const int kc = kk * 16 + 2 * c4;
            uint32_t ah[4][4], al[4][4], bh[4][2], bl[4][2];
#pragma unroll
            for (int nt = 0; nt < 4; nt++) {
                const int n0 = wn * 32 + nt * 8 + r4;
                bh[nt][0] = *(const uint32_t*)(sBh + n0 * SROW + kc);
                bh[nt][1] = *(const uint32_t*)(sBh + n0 * SROW + kc + 8);
                bl[nt][0] = *(const uint32_t*)(sBl + n0 * SROW + kc);
                bl[nt][1] = *(const uint32_t*)(sBl + n0 * SROW + kc + 8);
            }
#pragma unroll
            for (int mt = 0; mt < 4; mt++) {
                const int m0 = wm * 64 + mt * 16 + r4;
                ah[mt][0] = *(const uint32_t*)(sAh + m0 * SROW + kc);
                ah[mt][1] = *(const uint32_t*)(sAh + (m0 + 8) * SROW + kc);
                ah[mt][2] = *(const uint32_t*)(sAh + m0 * SROW + kc + 8);
                ah[mt][3] = *(const uint32_t*)(sAh + (m0 + 8) * SROW + kc + 8);
                al[mt][0] = *(const uint32_t*)(sAl + m0 * SROW + kc);
                al[mt][1] = *(const uint32_t*)(sAl + (m0 + 8) * SROW + kc);
                al[mt][2] = *(const uint32_t*)(sAl + m0 * SROW + kc + 8);
                al[mt][3] = *(const uint32_t*)(sAl + (m0 + 8) * SROW + kc + 8);
            }
#pragma unroll
            for (int mt = 0; mt < 4; mt++)
#pragma unroll
                for (int nt = 0; nt < 4; nt++)
                    mma_bf16(acc[mt][nt], ah[mt], bh[nt]);
#pragma unroll
            for (int mt = 0; mt < 4; mt++)
#pragma unroll
                for (int nt = 0; nt < 4; nt++)
                    mma_bf16(acc[mt][nt], ah[mt], bl[nt]);
#pragma unroll
            for (int mt = 0; mt < 4; mt++)
#pragma unroll
                for (int nt = 0; nt < 4; nt++)
                    mma_bf16(acc[mt][nt], al[mt], bh[nt]);
        }
        __syncthreads();
    }

#pragma unroll
    for (int mt = 0; mt < 4; mt++) {
#pragma unroll
        for (int nt = 0; nt < 4; nt++) {
            const int row0 = bm * 128 + wm * 64 + mt * 16 + r4;
            const int col  = bn * 128 + wn * 32 + nt * 8 + c4 * 2;
            float2 v0 = make_float2(acc[mt][nt][0], acc[mt][nt][1]);
            float2 v1 = make_float2(acc[mt][nt][2], acc[mt][nt][3]);
            if (EPI) {
                float2 bv = *(const float2*)(bias + col);
                float2 r0 = *(const float2*)(resid + (size_t)row0 * NC + col);
                float2 r1 = *(const float2*)(resid + (size_t)(row0 + 8) * NC + col);
                v0.x += bv.x + r0.x;  v0.y += bv.y + r0.y;
                v1.x += bv.x + r1.x;  v1.y += bv.y + r1.y;
            }
            *(float2*)(C + (size_t)row0 * NC + col)       = v0;
            *(float2*)(C + (size_t)(row0 + 8) * NC + col) = v1;
        }
    }
}

// ---------------------------------------------------------------------------
// Attention-fusion v5: TWO independent (s,head) groups per 128-thread block.
// Group g = warps {2g, 2g+1} -> SMSPs {0,1} / {2,3}: all 4 SMSPs busy
// (64-thread blocks pinned every warp to SMSP 0/1 via wid%4).
// Groups are decoupled via named barriers (bar.sync 1+g, 64); no block sync.
// Per-group logic identical to R12 v4 (best measured numerics).
// ---------------------------------------------------------------------------
#define NBS 68
#define GBAR(g) asm volatile("bar.sync %0, 64;" :: "r"((g) + 1) : "memory")

__global__ __launch_bounds__(128)
void attn_kernel(const float* __restrict__ hbuf,
                 const int32_t* __restrict__ routes,
                 __nv_bfloat16* __restrict__ fh,
                 __nv_bfloat16* __restrict__ fl)
{
    const int grp = threadIdx.x >> 6;        // 0..1
    const int t   = threadIdx.x & 63;
    const int s   = blockIdx.x * 2 + grp;
    const int hh  = blockIdx.y;

    __shared__ float nb[2][NK][NBS];
    __shared__ float q[2][HDD];
    __shared__ float sc[2][NK];
    __shared__ float wred[2][4];
    __shared__ int   rt[2][NK];

    rt[grp][t] = routes[(size_t)s * NK + t] & (SQ - 1);
    q[grp][t]  = hbuf[(size_t)s * DM + hh * HDD + t];
    GBAR(grp);

    // Coalesced gather: sub-group g4 (of 4) loads row p*4+g4, 16 lanes/row.
    const int g4 = t >> 4;
    const int i4 = (t & 15) * 4;
#pragma unroll
    for (int p = 0; p < 16; p++) {
        const int k = p * 4 + g4;
        const float* np = hbuf + (size_t)rt[grp][k] * DM + hh * HDD;
        *(float4*)&nb[grp][k][i4] = *(const float4*)(np + i4);
    }
    GBAR(grp);

    // Scores: thread t = neighbor t
    float dot = 0.f;
#pragma unroll
    for (int d0 = 0; d0 < HDD; d0 += 4) {
        float4 v  = *(const float4*)&nb[grp][t][d0];
        float4 qv = *(const float4*)&q[grp][d0];
        dot = fmaf(v.x, qv.x, dot);
        dot = fmaf(v.y, qv.y, dot);
        dot = fmaf(v.z, qv.z, dot);
        dot = fmaf(v.w, qv.w, dot);
    }
    const float st = dot * 0.125f;

    // Butterfly max within warp, exchange across the group's 2 warps.
    float m = st;
    m = fmaxf(m, __shfl_xor_sync(0xFFFFFFFF, m, 16));
    m = fmaxf(m, __shfl_xor_sync(0xFFFFFFFF, m, 8));
    m = fmaxf(m, __shfl_xor_sync(0xFFFFFFFF, m, 4));
    m = fmaxf(m, __shfl_xor_sync(0xFFFFFFFF, m, 2));
    m = fmaxf(m, __shfl_xor_sync(0xFFFFFFFF, m, 1));
    if ((t & 31) == 0) wred[grp][t >> 5] = m;
    GBAR(grp);
    const float mx = fmaxf(wred[grp][0], wred[grp][1]);

    const float wexp = __expf(st - mx);
    sc[grp][t] = wexp;

    float ss = wexp;
    ss += __shfl_xor_sync(0xFFFFFFFF, ss, 16);
    ss += __shfl_xor_sync(0xFFFFFFFF, ss, 8);
    ss += __shfl_xor_sync(0xFFFFFFFF, ss, 4);
    ss += __shfl_xor_sync(0xFFFFFFFF, ss, 2);
    ss += __shfl_xor_sync(0xFFFFFFFF, ss, 1);
    if ((t & 31) == 0) wred[grp][2 + (t >> 5)] = ss;
    GBAR(grp);
    const float sum = wred[grp][2] + wred[grp][3];

    // Weighted sum: thread t = head-dim t; weights via LDS.128 broadcast.
    float accv = 0.f;
#pragma unroll
    for (int k4 = 0; k4 < 16; k4++) {
        const float4 ws = *(const float4*)&sc[grp][k4 * 4];
        accv = fmaf(ws.x, nb[grp][k4 * 4 + 0][t], accv);
        accv = fmaf(ws.y, nb[grp][k4 * 4 + 1][t], accv);
        accv = fmaf(ws.z, nb[grp][k4 * 4 + 2][t], accv);
        accv = fmaf(ws.w, nb[grp][k4 * 4 + 3][t], accv);
    }
    const float val = accv / sum;
    const size_t idx = (size_t)s * DM + hh * HDD + t;
    __nv_bfloat16 hv = __float2bfloat16(val);
    fh[idx] = hv;
    fl[idx] = __float2bfloat16(val - __bfloat162float(hv));
}

// ---------------------------------------------------------------------------
// Launch
// ---------------------------------------------------------------------------
extern "C" void kernel_launch(void* const* d_in, const int* in_sizes, int n_in,
                              void* d_out, int out_size)
{
    const float*   x      = nullptr;
    const int32_t* routes = nullptr;
    const float*   W_in   = nullptr;
    const float*   W_out  = nullptr;
    const float*   b_out  = nullptr;

    for (int i = 0; i < n_in; i++) {
        const int sz = in_sizes[i];
        if      (sz == SQ * DM)  { x = (const float*)d_in[i]; }
        else if (sz == SQ * NK)  { routes = (const int32_t*)d_in[i]; }
        else if (sz == DM * DM)  { if (!W_in) W_in = (const float*)d_in[i];
                                   else       W_out = (const float*)d_in[i]; }
        else if (sz == DM)       { b_out = (const float*)d_in[i]; }
    }
    float* out = (float*)d_out;

    float *hbuf;
    __nv_bfloat16 *xh, *xl, *wih, *wil, *woh, *wol, *fh, *fl;
    cudaGetSymbolAddress((void**)&hbuf, g_h);
    cudaGetSymbolAddress((void**)&xh,  g_xh);  cudaGetSymbolAddress((void**)&xl,  g_xl);
    cudaGetSymbolAddress((void**)&wih, g_wih); cudaGetSymbolAddress((void**)&wil, g_wil);
    cudaGetSymbolAddress((void**)&woh, g_woh); cudaGetSymbolAddress((void**)&wol, g_wol);
    cudaGetSymbolAddress((void**)&fh,  g_fh);  cudaGetSymbolAddress((void**)&fl,  g_fl);

    cudaFuncSetAttribute(gemm_bf16x3<false>,
                         cudaFuncAttributeMaxDynamicSharedMemorySize, GSMEM);
    cudaFuncSetAttribute(gemm_bf16x3<true>,
                         cudaFuncAttributeMaxDynamicSharedMemorySize, GSMEM);

    cvt_all<<<(SQ * DM + 2 * DM * DM) / 1024, 256>>>(x, W_in, W_out,
                                                     xh, xl, wih, wil, woh, wol);

    dim3 gGemm(DM / 128, SQ / 128);   // (8, 16)

    gemm_bf16x3<false><<<gGemm, 256, GSMEM>>>(xh, xl, wih, wil, hbuf,
                                              nullptr, nullptr);
    attn_kernel<<<dim3(SQ / 2, NH), 128>>>(hbuf, routes, fh, fl);
    gemm_bf16x3<true><<<gGemm, 256, GSMEM>>>(fh, fl, woh, wol, out, b_out, x);
}

// round 14
// speedup vs baseline: 1.1382x; 1.1382x over previous
#include <cuda_runtime.h>
#include <cuda_bf16.h>
#include <stdint.h>

#define SQ   2048
#define DM   1024
#define NH   16
#define HDD  64
#define NK   64

// fp32 hidden buffer (attn gathers from this)
__device__ float g_h[SQ * DM];
// bf16 hi/lo operand copies
__device__ __nv_bfloat16 g_xh[SQ * DM], g_xl[SQ * DM];
__device__ __nv_bfloat16 g_wih[DM * DM], g_wil[DM * DM];
__device__ __nv_bfloat16 g_woh[DM * DM], g_wol[DM * DM];
__device__ __nv_bfloat16 g_fh[SQ * DM], g_fl[SQ * DM];

// ---------------------------------------------------------------------------
// Single-launch split of {x, W_in, W_out} into bf16 hi/lo.
// ---------------------------------------------------------------------------
__global__ __launch_bounds__(256)
void cvt_all(const float* __restrict__ x,
             const float* __restrict__ wi,
             const float* __restrict__ wo,
             __nv_bfloat16* __restrict__ xh, __nv_bfloat16* __restrict__ xl,
             __nv_bfloat16* __restrict__ wih, __nv_bfloat16* __restrict__ wil,
             __nv_bfloat16* __restrict__ woh, __nv_bfloat16* __restrict__ wol)
{
    const int i = (blockIdx.x * 256 + threadIdx.x) * 4;
    const float* src;
    __nv_bfloat16 *hi, *lo;
    int off;
    if (i < SQ * DM)              { src = x;  hi = xh;  lo = xl;  off = i; }
    else if (i < SQ * DM + DM*DM) { src = wi; hi = wih; lo = wil; off = i - SQ * DM; }
    else                          { src = wo; hi = woh; lo = wol; off = i - SQ * DM - DM * DM; }

    float4 v = *(const float4*)(src + off);
    __nv_bfloat16 h0 = __float2bfloat16(v.x);
    __nv_bfloat16 h1 = __float2bfloat16(v.y);
    __nv_bfloat16 h2 = __float2bfloat16(v.z);
    __nv_bfloat16 h3 = __float2bfloat16(v.w);
    __nv_bfloat162 hv0; hv0.x = h0; hv0.y = h1;
    __nv_bfloat162 hv1; hv1.x = h2; hv1.y = h3;
    __nv_bfloat162 lv0, lv1;
    lv0.x = __float2bfloat16(v.x - __bfloat162float(h0));
    lv0.y = __float2bfloat16(v.y - __bfloat162float(h1));
    lv1.x = __float2bfloat16(v.z - __bfloat162float(h2));
    lv1.y = __float2bfloat16(v.w - __bfloat162float(h3));
    *(__nv_bfloat162*)(hi + off)     = hv0;
    *(__nv_bfloat162*)(hi + off + 2) = hv1;
    *(__nv_bfloat162*)(lo + off)     = lv0;
    *(__nv_bfloat162*)(lo + off + 2) = lv1;
}

// ---------------------------------------------------------------------------
// bf16x3 NT GEMM: exact R5 inner loop (inline frag loads, interleaved
// splits -- fastest measured), NOW with a 3-stage cp.async ring:
// one __syncthreads per stage instead of two, 2 stages prefetched.
// Stage-s writes hit buffer (s+2)%3 == (s-1)%3, whose readers all passed
// this stage's sync -- safe with a single barrier.
// ---------------------------------------------------------------------------
#define SROW 40
#define AELEM (128 * SROW)
#define BUFELEM (4 * AELEM)
#define GSMEM (3 * BUFELEM * 2)      // 122880 B

__device__ __forceinline__ void cp16(uint32_t sdst, const void* gsrc) {
    asm volatile("cp.async.cg.shared.global [%0], [%1], 16;" ::
                 "r"(sdst), "l"(gsrc));
}
__device__ __forceinline__ void cp_commit() {
    asm volatile("cp.async.commit_group;");
}
__device__ __forceinline__ void mma_bf16(float* c, const uint32_t* a, const uint32_t* b) {
    asm volatile(
        "mma.sync.aligned.m16n8k16.row.col.f32.bf16.bf16.f32 "
        "{%0,%1,%2,%3}, {%4,%5,%6,%7}, {%8,%9}, {%0,%1,%2,%3};"
        : "+f"(c[0]), "+f"(c[1]), "+f"(c[2]), "+f"(c[3])
        : "r"(a[0]), "r"(a[1]), "r"(a[2]), "r"(a[3]), "r"(b[0]), "r"(b[1]));
}

template <bool EPI>
__global__ __launch_bounds__(256, 1)
void gemm_bf16x3(const __nv_bfloat16* __restrict__ Ah,
                 const __nv_bfloat16* __restrict__ Al,
                 const __nv_bfloat16* __restrict__ Bh,
                 const __nv_bfloat16* __restrict__ Bl,
                 float* __restrict__ C,
                 const float* __restrict__ bias,
                 const float* __restrict__ resid)
{
    constexpr int KD = 1024, NC = 1024, NS = 32;

    extern __shared__ __nv_bfloat16 sm[];
    uint32_t sbase;
    asm("{ .reg .u64 t; cvta.to.shared.u64 t, %1; cvt.u32.u64 %0, t; }"
        : "=r"(sbase) : "l"(sm));

    const int t    = threadIdx.x;
    const int lane = t & 31;
    const int w    = t >> 5;
    const int wm   = w >> 2;
    const int wn   = w & 3;
    const int bm   = blockIdx.y;
    const int bn   = blockIdx.x;
    const int r4   = lane >> 2;
    const int c4   = lane & 3;

    const __nv_bfloat16* gsrc[4] = {
        Ah + (size_t)(bm * 128) * KD, Al + (size_t)(bm * 128) * KD,
        Bh + (size_t)(bn * 128) * KD, Bl + (size_t)(bn * 128) * KD };

    float acc[4][4][4];
#pragma unroll
    for (int i = 0; i < 4; i++)
#pragma unroll
        for (int j = 0; j < 4; j++)
#pragma unroll
            for (int q = 0; q < 4; q++) acc[i][j][q] = 0.f;

    auto issue_stage = [&](int ks, int buf) {
        const int k0 = ks * 32;
#pragma unroll
        for (int arr = 0; arr < 4; arr++) {
            const uint32_t ab = sbase + (uint32_t)(buf * BUFELEM + arr * AELEM) * 2;
            const __nv_bfloat16* src = gsrc[arr];
#pragma unroll
            for (int i = 0; i < 2; i++) {
                const int c = t + i * 256;
                const int row = c >> 2, j = c & 3;
                cp16(ab + (uint32_t)(row * SROW + j * 8) * 2,
                     src + (size_t)row * KD + k0 + j * 8);
            }
        }
        cp_commit();
    };

    issue_stage(0, 0);
    issue_stage(1, 1);

    for (int ks = 0; ks < NS; ks++) {
        const int buf = ks % 3;
        if (ks + 1 < NS) asm volatile("cp.async.wait_group 1;" ::: "memory");
        else             asm volatile("cp.async.wait_group 0;" ::: "memory");
        __syncthreads();                       // single barrier per stage
        if (ks + 2 < NS) issue_stage(ks + 2, (ks + 2) % 3);

        const __nv_bfloat16* sAh = sm + buf * BUFELEM;
        const __nv_bfloat16* sAl = sAh + AELEM;
        const __nv_bfloat16* sBh = sAl + AELEM;
        const __nv_bfloat16* sBl = sBh + AELEM;

#pragma unroll
        for (int kk = 0; kk < 2; kk++) {
            const int kc = kk * 16 + 2 * c4;
            uint32_t bh[4][2], bl[4][2];
#pragma unroll
            for (int nt = 0; nt < 4; nt++) {
                const int n0 = wn * 32 + nt * 8 + r4;
                bh[nt][0] = *(const uint32_t*)(sBh + n0 * SROW + kc);
                bh[nt][1] = *(const uint32_t*)(sBh + n0 * SROW + kc + 8);
                bl[nt][0] = *(const uint32_t*)(sBl + n0 * SROW + kc);
                bl[nt][1] = *(const uint32_t*)(sBl + n0 * SROW + kc + 8);
            }
#pragma unroll
            for (int mt = 0; mt < 4; mt++) {
                const int m0 = wm * 64 + mt * 16 + r4;
                uint32_t ah[4], al[4];
                ah[0] = *(const uint32_t*)(sAh + m0 * SROW + kc);
                ah[1] = *(const uint32_t*)(sAh + (m0 + 8) * SROW + kc);
                ah[2] = *(const uint32_t*)(sAh + m0 * SROW + kc + 8);
                ah[3] = *(const uint32_t*)(sAh + (m0 + 8) * SROW + kc + 8);
                al[0] = *(const uint32_t*)(sAl + m0 * SROW + kc);
                al[1] = *(const uint32_t*)(sAl + (m0 + 8) * SROW + kc);
                al[2] = *(const uint32_t*)(sAl + m0 * SROW + kc + 8);
                al[3] = *(const uint32_t*)(sAl + (m0 + 8) * SROW + kc + 8);
#pragma unroll
                for (int nt = 0; nt < 4; nt++) {
                    mma_bf16(acc[mt][nt], ah, bh[nt]);
                    mma_bf16(acc[mt][nt], ah, bl[nt]);
                    mma_bf16(acc[mt][nt], al, bh[nt]);
                }
            }
        }
    }

#pragma unroll
    for (int mt = 0; mt < 4; mt++) {
#pragma unroll
        for (int nt = 0; nt < 4; nt++) {
            const int row0 = bm * 128 + wm * 64 + mt * 16 + r4;
            const int col  = bn * 128 + wn * 32 + nt * 8 + c4 * 2;
            float2 v0 = make_float2(acc[mt][nt][0], acc[mt][nt][1]);
            float2 v1 = make_float2(acc[mt][nt][2], acc[mt][nt][3]);
            if (EPI) {
                float2 bv = *(const float2*)(bias + col);
                float2 r0 = *(const float2*)(resid + (size_t)row0 * NC + col);
                float2 r1 = *(const float2*)(resid + (size_t)(row0 + 8) * NC + col);
                v0.x += bv.x + r0.x;  v0.y += bv.y + r0.y;
                v1.x += bv.x + r1.x;  v1.y += bv.y + r1.y;
            }
            *(float2*)(C + (size_t)row0 * NC + col)       = v0;
            *(float2*)(C + (size_t)(row0 + 8) * NC + col) = v1;
        }
    }
}

// ---------------------------------------------------------------------------
// Attention-fusion v4 (exact R12 best): 64-thread blocks, coalesced gather,
// butterfly max + sum, __expf, LDS.128 weight broadcasts.
// ---------------------------------------------------------------------------
#define NBS 68
__global__ __launch_bounds__(64)
void attn_kernel(const float* __restrict__ hbuf,
                 const int32_t* __restrict__ routes,
                 __nv_bfloat16* __restrict__ fh,
                 __nv_bfloat16* __restrict__ fl)
{
    const int s  = blockIdx.x;
    const int hh = blockIdx.y;
    const int t  = threadIdx.x;

    __shared__ float nb[NK][NBS];
    __shared__ float q[HDD];
    __shared__ float sc[NK];
    __shared__ float wred[4];
    __shared__ int   rt[NK];

    rt[t] = routes[(size_t)s * NK + t] & (SQ - 1);
    q[t]  = hbuf[(size_t)s * DM + hh * HDD + t];
    __syncthreads();

    const int g = t >> 4;
    const int i4 = (t & 15) * 4;
#pragma unroll
    for (int p = 0; p < 16; p++) {
        const int k = p * 4 + g;
        const float* np = hbuf + (size_t)rt[k] * DM + hh * HDD;
        *(float4*)&nb[k][i4] = *(const float4*)(np + i4);
    }
    __syncthreads();

    float dot = 0.f;
#pragma unroll
    for (int d0 = 0; d0 < HDD; d0 += 4) {
        float4 v  = *(const float4*)&nb[t][d0];
        float4 qv = *(const float4*)&q[d0];
        dot = fmaf(v.x, qv.x, dot);
        dot = fmaf(v.y, qv.y, dot);
        dot = fmaf(v.z, qv.z, dot);
        dot = fmaf(v.w, qv.w, dot);
    }
    const float st = dot * 0.125f;

    float m = st;
    m = fmaxf(m, __shfl_xor_sync(0xFFFFFFFF, m, 16));
    m = fmaxf(m, __shfl_xor_sync(0xFFFFFFFF, m, 8));
    m = fmaxf(m, __shfl_xor_sync(0xFFFFFFFF, m, 4));
    m = fmaxf(m, __shfl_xor_sync(0xFFFFFFFF, m, 2));
    m = fmaxf(m, __shfl_xor_sync(0xFFFFFFFF, m, 1));
    if ((t & 31) == 0) wred[t >> 5] = m;
    __syncthreads();
    const float mx = fmaxf(wred[0], wred[1]);

    const float wexp = __expf(st - mx);
    sc[t] = wexp;

    float ss = wexp;
    ss += __shfl_xor_sync(0xFFFFFFFF, ss, 16);
    ss += __shfl_xor_sync(0xFFFFFFFF, ss, 8);
    ss += __shfl_xor_sync(0xFFFFFFFF, ss, 4);
    ss += __shfl_xor_sync(0xFFFFFFFF, ss, 2);
    ss += __shfl_xor_sync(0xFFFFFFFF, ss, 1);
    if ((t & 31) == 0) wred[2 + (t >> 5)] = ss;
    __syncthreads();
    const float sum = wred[2] + wred[3];

    float accv = 0.f;
#pragma unroll
    for (int k4 = 0; k4 < 16; k4++) {
        const float4 ws = *(const float4*)&sc[k4 * 4];
        accv = fmaf(ws.x, nb[k4 * 4 + 0][t], accv);
        accv = fmaf(ws.y, nb[k4 * 4 + 1][t], accv);
        accv = fmaf(ws.z, nb[k4 * 4 + 2][t], accv);
        accv = fmaf(ws.w, nb[k4 * 4 + 3][t], accv);
    }
    const float val = accv / sum;
    const size_t idx = (size_t)s * DM + hh * HDD + t;
    __nv_bfloat16 hv = __float2bfloat16(val);
    fh[idx] = hv;
    fl[idx] = __float2bfloat16(val - __bfloat162float(hv));
}

// ---------------------------------------------------------------------------
// Launch
// ---------------------------------------------------------------------------
extern "C" void kernel_launch(void* const* d_in, const int* in_sizes, int n_in,
                              void* d_out, int out_size)
{
    const float*   x      = nullptr;
    const int32_t* routes = nullptr;
    const float*   W_in   = nullptr;
    const float*   W_out  = nullptr;
    const float*   b_out  = nullptr;

    for (int i = 0; i < n_in; i++) {
        const int sz = in_sizes[i];
        if      (sz == SQ * DM)  { x = (const float*)d_in[i]; }
        else if (sz == SQ * NK)  { routes = (const int32_t*)d_in[i]; }
        else if (sz == DM * DM)  { if (!W_in) W_in = (const float*)d_in[i];
                                   else       W_out = (const float*)d_in[i]; }
        else if (sz == DM)       { b_out = (const float*)d_in[i]; }
    }
    float* out = (float*)d_out;

    float *hbuf;
    __nv_bfloat16 *xh, *xl, *wih, *wil, *woh, *wol, *fh, *fl;
    cudaGetSymbolAddress((void**)&hbuf, g_h);
    cudaGetSymbolAddress((void**)&xh,  g_xh);  cudaGetSymbolAddress((void**)&xl,  g_xl);
    cudaGetSymbolAddress((void**)&wih, g_wih); cudaGetSymbolAddress((void**)&wil, g_wil);
    cudaGetSymbolAddress((void**)&woh, g_woh); cudaGetSymbolAddress((void**)&wol, g_wol);
    cudaGetSymbolAddress((void**)&fh,  g_fh);  cudaGetSymbolAddress((void**)&fl,  g_fl);

    cudaFuncSetAttribute(gemm_bf16x3<false>,
                         cudaFuncAttributeMaxDynamicSharedMemorySize, GSMEM);
    cudaFuncSetAttribute(gemm_bf16x3<true>,
                         cudaFuncAttributeMaxDynamicSharedMemorySize, GSMEM);

    cvt_all<<<(SQ * DM + 2 * DM * DM) / 1024, 256>>>(x, W_in, W_out,
                                                     xh, xl, wih, wil, woh, wol);

    dim3 gGemm(DM / 128, SQ / 128);   // (8, 16)

    gemm_bf16x3<false><<<gGemm, 256, GSMEM>>>(xh, xl, wih, wil, hbuf,
                                              nullptr, nullptr);
    attn_kernel<<<dim3(SQ, NH), 64>>>(hbuf, routes, fh, fl);
    gemm_bf16x3<true><<<gGemm, 256, GSMEM>>>(fh, fl, woh, wol, out, b_out, x);
}

// round 16
// speedup vs baseline: 1.1407x; 1.0022x over previous
#include <cuda_runtime.h>
#include <cuda_bf16.h>
#include <stdint.h>

#define SQ   2048
#define DM   1024
#define NH   16
#define HDD  64
#define NK   64

// fp32 hidden buffer (attn gathers from this)
__device__ float g_h[SQ * DM];
// bf16 hi/lo operand copies
__device__ __nv_bfloat16 g_xh[SQ * DM], g_xl[SQ * DM];
__device__ __nv_bfloat16 g_wih[DM * DM], g_wil[DM * DM];
__device__ __nv_bfloat16 g_woh[DM * DM], g_wol[DM * DM];
__device__ __nv_bfloat16 g_fh[SQ * DM], g_fl[SQ * DM];

// ---------------------------------------------------------------------------
// Single-launch split of {x, W_in, W_out} into bf16 hi/lo.
// ---------------------------------------------------------------------------
__global__ __launch_bounds__(256)
void cvt_all(const float* __restrict__ x,
             const float* __restrict__ wi,
             const float* __restrict__ wo,
             __nv_bfloat16* __restrict__ xh, __nv_bfloat16* __restrict__ xl,
             __nv_bfloat16* __restrict__ wih, __nv_bfloat16* __restrict__ wil,
             __nv_bfloat16* __restrict__ woh, __nv_bfloat16* __restrict__ wol)
{
    const int i = (blockIdx.x * 256 + threadIdx.x) * 4;
    const float* src;
    __nv_bfloat16 *hi, *lo;
    int off;
    if (i < SQ * DM)              { src = x;  hi = xh;  lo = xl;  off = i; }
    else if (i < SQ * DM + DM*DM) { src = wi; hi = wih; lo = wil; off = i - SQ * DM; }
    else                          { src = wo; hi = woh; lo = wol; off = i - SQ * DM - DM * DM; }

    float4 v = *(const float4*)(src + off);
    __nv_bfloat16 h0 = __float2bfloat16(v.x);
    __nv_bfloat16 h1 = __float2bfloat16(v.y);
    __nv_bfloat16 h2 = __float2bfloat16(v.z);
    __nv_bfloat16 h3 = __float2bfloat16(v.w);
    __nv_bfloat162 hv0; hv0.x = h0; hv0.y = h1;
    __nv_bfloat162 hv1; hv1.x = h2; hv1.y = h3;
    __nv_bfloat162 lv0, lv1;
    lv0.x = __float2bfloat16(v.x - __bfloat162float(h0));
    lv0.y = __float2bfloat16(v.y - __bfloat162float(h1));
    lv1.x = __float2bfloat16(v.z - __bfloat162float(h2));
    lv1.y = __float2bfloat16(v.w - __bfloat162float(h3));
    *(__nv_bfloat162*)(hi + off)     = hv0;
    *(__nv_bfloat162*)(hi + off + 2) = hv1;
    *(__nv_bfloat162*)(lo + off)     = lv0;
    *(__nv_bfloat162*)(lo + off + 2) = lv1;
}

// ---------------------------------------------------------------------------
// bf16x3 NT GEMM: R5-form inner loop, 2-stage cp.async ring,
// __launch_bounds__(256, 2) caps regs at 128 so TWO independent CTAs fit
// per SM (regfile was the limiter at 140 regs). Second CTA fills the
// wait/barrier bubbles of the first.
// ---------------------------------------------------------------------------
#define SROW 40
#define AELEM (128 * SROW)
#define BUFELEM (4 * AELEM)
#define GSMEM (2 * BUFELEM * 2)     // 81920 B; 2 CTAs = 163840 <= 228KB

__device__ __forceinline__ void cp16(uint32_t sdst, const void* gsrc) {
    asm volatile("cp.async.cg.shared.global [%0], [%1], 16;" ::
                 "r"(sdst), "l"(gsrc));
}
__device__ __forceinline__ void cp_commit() {
    asm volatile("cp.async.commit_group;");
}
__device__ __forceinline__ void mma_bf16(float* c, const uint32_t* a, const uint32_t* b) {
    asm volatile(
        "mma.sync.aligned.m16n8k16.row.col.f32.bf16.bf16.f32 "
        "{%0,%1,%2,%3}, {%4,%5,%6,%7}, {%8,%9}, {%0,%1,%2,%3};"
        : "+f"(c[0]), "+f"(c[1]), "+f"(c[2]), "+f"(c[3])
        : "r"(a[0]), "r"(a[1]), "r"(a[2]), "r"(a[3]), "r"(b[0]), "r"(b[1]));
}

template <bool EPI>
__global__ __launch_bounds__(256, 2)
void gemm_bf16x3(const __nv_bfloat16* __restrict__ Ah,
                 const __nv_bfloat16* __restrict__ Al,
                 const __nv_bfloat16* __restrict__ Bh,
                 const __nv_bfloat16* __restrict__ Bl,
                 float* __restrict__ C,
                 const float* __restrict__ bias,
                 const float* __restrict__ resid)
{
    constexpr int KD = 1024, NC = 1024, NS = 32;

    extern __shared__ __nv_bfloat16 sm[];
    uint32_t sbase;
    asm("{ .reg .u64 t; cvta.to.shared.u64 t, %1; cvt.u32.u64 %0, t; }"
        : "=r"(sbase) : "l"(sm));

    const int t    = threadIdx.x;
    const int lane = t & 31;
    const int w    = t >> 5;
    const int wm   = w >> 2;
    const int wn   = w & 3;
    const int bm   = blockIdx.y;
    const int bn   = blockIdx.x;
    const int r4   = lane >> 2;
    const int c4   = lane & 3;

    const __nv_bfloat16* gsrc[4] = {
        Ah + (size_t)(bm * 128) * KD, Al + (size_t)(bm * 128) * KD,
        Bh + (size_t)(bn * 128) * KD, Bl + (size_t)(bn * 128) * KD };

    float acc[4][4][4];
#pragma unroll
    for (int i = 0; i < 4; i++)
#pragma unroll
        for (int j = 0; j < 4; j++)
#pragma unroll
            for (int q = 0; q < 4; q++) acc[i][j][q] = 0.f;

    auto issue_stage = [&](int ks, int buf) {
        const int k0 = ks * 32;
#pragma unroll
        for (int arr = 0; arr < 4; arr++) {
            const uint32_t ab = sbase + (uint32_t)(buf * BUFELEM + arr * AELEM) * 2;
            const __nv_bfloat16* src = gsrc[arr];
#pragma unroll
            for (int i = 0; i < 2; i++) {
                const int c = t + i * 256;
                const int row = c >> 2, j = c & 3;
                cp16(ab + (uint32_t)(row * SROW + j * 8) * 2,
                     src + (size_t)row * KD + k0 + j * 8);
            }
        }
        cp_commit();
    };

    issue_stage(0, 0);

    for (int ks = 0; ks < NS; ks++) {
        const int buf = ks & 1;
        if (ks + 1 < NS) {
            issue_stage(ks + 1, buf ^ 1);
            asm volatile("cp.async.wait_group 1;");
        } else {
            asm volatile("cp.async.wait_group 0;");
        }
        __syncthreads();

        const __nv_bfloat16* sAh = sm + buf * BUFELEM;
        const __nv_bfloat16* sAl = sAh + AELEM;
        const __nv_bfloat16* sBh = sAl + AELEM;
        const __nv_bfloat16* sBl = sBh + AELEM;

#pragma unroll
        for (int kk = 0; kk < 2; kk++) {
            const int kc = kk * 16 + 2 * c4;
            uint32_t bh[4][2], bl[4][2];
#pragma unroll
            for (int nt = 0; nt < 4; nt++) {
                const int n0 = wn * 32 + nt * 8 + r4;
                bh[nt][0] = *(const uint32_t*)(sBh + n0 * SROW + kc);
                bh[nt][1] = *(const uint32_t*)(sBh + n0 * SROW + kc + 8);
                bl[nt][0] = *(const uint32_t*)(sBl + n0 * SROW + kc);
                bl[nt][1] = *(const uint32_t*)(sBl + n0 * SROW + kc + 8);
            }
#pragma unroll
            for (int mt = 0; mt < 4; mt++) {
                const int m0 = wm * 64 + mt * 16 + r4;
                uint32_t ah[4], al[4];
                ah[0] = *(const uint32_t*)(sAh + m0 * SROW + kc);
                ah[1] = *(const uint32_t*)(sAh + (m0 + 8) * SROW + kc);
                ah[2] = *(const uint32_t*)(sAh + m0 * SROW + kc + 8);
                ah[3] = *(const uint32_t*)(sAh + (m0 + 8) * SROW + kc + 8);
                al[0] = *(const uint32_t*)(sAl + m0 * SROW + kc);
                al[1] = *(const uint32_t*)(sAl + (m0 + 8) * SROW + kc);
                al[2] = *(const uint32_t*)(sAl + m0 * SROW + kc + 8);
                al[3] = *(const uint32_t*)(sAl + (m0 + 8) * SROW + kc + 8);
#pragma unroll
                for (int nt = 0; nt < 4; nt++) {
                    mma_bf16(acc[mt][nt], ah, bh[nt]);
                    mma_bf16(acc[mt][nt], ah, bl[nt]);
                    mma_bf16(acc[mt][nt], al, bh[nt]);
                }
            }
        }
        __syncthreads();
    }

#pragma unroll
    for (int mt = 0; mt < 4; mt++) {
#pragma unroll
        for (int nt = 0; nt < 4; nt++) {
            const int row0 = bm * 128 + wm * 64 + mt * 16 + r4;
            const int col  = bn * 128 + wn * 32 + nt * 8 + c4 * 2;
            float2 v0 = make_float2(acc[mt][nt][0], acc[mt][nt][1]);
            float2 v1 = make_float2(acc[mt][nt][2], acc[mt][nt][3]);
            if (EPI) {
                float2 bv = *(const float2*)(bias + col);
                float2 r0 = *(const float2*)(resid + (size_t)row0 * NC + col);
                float2 r1 = *(const float2*)(resid + (size_t)(row0 + 8) * NC + col);
                v0.x += bv.x + r0.x;  v0.y += bv.y + r0.y;
                v1.x += bv.x + r1.x;  v1.y += bv.y + r1.y;
            }
            *(float2*)(C + (size_t)row0 * NC + col)       = v0;
            *(float2*)(C + (size_t)(row0 + 8) * NC + col) = v1;
        }
    }
}

// ---------------------------------------------------------------------------
// Attention-fusion v4 (exact R12 best): 64-thread blocks, coalesced gather,
// butterfly max + sum, __expf, LDS.128 weight broadcasts.
// ---------------------------------------------------------------------------
#define NBS 68
__global__ __launch_bounds__(64)
void attn_kernel(const float* __restrict__ hbuf,
                 const int32_t* __restrict__ routes,
                 __nv_bfloat16* __restrict__ fh,
                 __nv_bfloat16* __restrict__ fl)
{
    const int s  = blockIdx.x;
    const int hh = blockIdx.y;
    const int t  = threadIdx.x;

    __shared__ float nb[NK][NBS];
    __shared__ float q[HDD];
    __shared__ float sc[NK];
    __shared__ float wred[4];
    __shared__ int   rt[NK];

    rt[t] = routes[(size_t)s * NK + t] & (SQ - 1);
    q[t]  = hbuf[(size_t)s * DM + hh * HDD + t];
    __syncthreads();

    const int g = t >> 4;
    const int i4 = (t & 15) * 4;
#pragma unroll
    for (int p = 0; p < 16; p++) {
        const int k = p * 4 + g;
        const float* np = hbuf + (size_t)rt[k] * DM + hh * HDD;
        *(float4*)&nb[k][i4] = *(const float4*)(np + i4);
    }
    __syncthreads();

    float dot = 0.f;
#pragma unroll
    for (int d0 = 0; d0 < HDD; d0 += 4) {
        float4 v  = *(const float4*)&nb[t][d0];
        float4 qv = *(const float4*)&q[d0];
        dot = fmaf(v.x, qv.x, dot);
        dot = fmaf(v.y, qv.y, dot);
        dot = fmaf(v.z, qv.z, dot);
        dot = fmaf(v.w, qv.w, dot);
    }
    const float st = dot * 0.125f;

    float m = st;
    m = fmaxf(m, __shfl_xor_sync(0xFFFFFFFF, m, 16));
    m = fmaxf(m, __shfl_xor_sync(0xFFFFFFFF, m, 8));
    m = fmaxf(m, __shfl_xor_sync(0xFFFFFFFF, m, 4));
    m = fmaxf(m, __shfl_xor_sync(0xFFFFFFFF, m, 2));
    m = fmaxf(m, __shfl_xor_sync(0xFFFFFFFF, m, 1));
    if ((t & 31) == 0) wred[t >> 5] = m;
    __syncthreads();
    const float mx = fmaxf(wred[0], wred[1]);

    const float wexp = __expf(st - mx);
    sc[t] = wexp;

    float ss = wexp;
    ss += __shfl_xor_sync(0xFFFFFFFF, ss, 16);
    ss += __shfl_xor_sync(0xFFFFFFFF, ss, 8);
    ss += __shfl_xor_sync(0xFFFFFFFF, ss, 4);
    ss += __shfl_xor_sync(0xFFFFFFFF, ss, 2);
    ss += __shfl_xor_sync(0xFFFFFFFF, ss, 1);
    if ((t & 31) == 0) wred[2 + (t >> 5)] = ss;
    __syncthreads();
    const float sum = wred[2] + wred[3];

    float accv = 0.f;
#pragma unroll
    for (int k4 = 0; k4 < 16; k4++) {
        const float4 ws = *(const float4*)&sc[k4 * 4];
        accv = fmaf(ws.x, nb[k4 * 4 + 0][t], accv);
        accv = fmaf(ws.y, nb[k4 * 4 + 1][t], accv);
        accv = fmaf(ws.z, nb[k4 * 4 + 2][t], accv);
        accv = fmaf(ws.w, nb[k4 * 4 + 3][t], accv);
    }
    const float val = accv / sum;
    const size_t idx = (size_t)s * DM + hh * HDD + t;
    __nv_bfloat16 hv = __float2bfloat16(val);
    fh[idx] = hv;
    fl[idx] = __float2bfloat16(val - __bfloat162float(hv));
}

// ---------------------------------------------------------------------------
// Launch
// ---------------------------------------------------------------------------
extern "C" void kernel_launch(void* const* d_in, const int* in_sizes, int n_in,
                              void* d_out, int out_size)
{
    const float*   x      = nullptr;
    const int32_t* routes = nullptr;
    const float*   W_in   = nullptr;
    const float*   W_out  = nullptr;
    const float*   b_out  = nullptr;

    for (int i = 0; i < n_in; i++) {
        const int sz = in_sizes[i];
        if      (sz == SQ * DM)  { x = (const float*)d_in[i]; }
        else if (sz == SQ * NK)  { routes = (const int32_t*)d_in[i]; }
        else if (sz == DM * DM)  { if (!W_in) W_in = (const float*)d_in[i];
                                   else       W_out = (const float*)d_in[i]; }
        else if (sz == DM)       { b_out = (const float*)d_in[i]; }
    }
    float* out = (float*)d_out;

    float *hbuf;
    __nv_bfloat16 *xh, *xl, *wih, *wil, *woh, *wol, *fh, *fl;
    cudaGetSymbolAddress((void**)&hbuf, g_h);
    cudaGetSymbolAddress((void**)&xh,  g_xh);  cudaGetSymbolAddress((void**)&xl,  g_xl);
    cudaGetSymbolAddress((void**)&wih, g_wih); cudaGetSymbolAddress((void**)&wil, g_wil);
    cudaGetSymbolAddress((void**)&woh, g_woh); cudaGetSymbolAddress((void**)&wol, g_wol);
    cudaGetSymbolAddress((void**)&fh,  g_fh);  cudaGetSymbolAddress((void**)&fl,  g_fl);

    cudaFuncSetAttribute(gemm_bf16x3<false>,
                         cudaFuncAttributeMaxDynamicSharedMemorySize, GSMEM);
    cudaFuncSetAttribute(gemm_bf16x3<true>,
                         cudaFuncAttributeMaxDynamicSharedMemorySize, GSMEM);

    cvt_all<<<(SQ * DM + 2 * DM * DM) / 1024, 256>>>(x, W_in, W_out,
                                                     xh, xl, wih, wil, woh, wol);

    dim3 gGemm(DM / 128, SQ / 128);   // (8, 16)

    gemm_bf16x3<false><<<gGemm, 256, GSMEM>>>(xh, xl, wih, wil, hbuf,
                                              nullptr, nullptr);
    attn_kernel<<<dim3(SQ, NH), 64>>>(hbuf, routes, fh, fl);
    gemm_bf16x3<true><<<gGemm, 256, GSMEM>>>(fh, fl, woh, wol, out, b_out, x);
}

// round 17
// speedup vs baseline: 1.3433x; 1.1777x over previous
#include <cuda_runtime.h>
#include <cuda_bf16.h>
#include <stdint.h>

#define SQ   2048
#define DM   1024
#define NH   16
#define HDD  64
#define NK   64

// fp32 hidden buffer (attn gathers from this)
__device__ float g_h[SQ * DM];
// bf16 hi/lo operand copies
__device__ __nv_bfloat16 g_xh[SQ * DM], g_xl[SQ * DM];
__device__ __nv_bfloat16 g_wih[DM * DM], g_wil[DM * DM];
__device__ __nv_bfloat16 g_woh[DM * DM], g_wol[DM * DM];
__device__ __nv_bfloat16 g_fh[SQ * DM], g_fl[SQ * DM];

// ---------------------------------------------------------------------------
// Single-launch split of {x, W_in, W_out} into bf16 hi/lo.
// ---------------------------------------------------------------------------
__global__ __launch_bounds__(256)
void cvt_all(const float* __restrict__ x,
             const float* __restrict__ wi,
             const float* __restrict__ wo,
             __nv_bfloat16* __restrict__ xh, __nv_bfloat16* __restrict__ xl,
             __nv_bfloat16* __restrict__ wih, __nv_bfloat16* __restrict__ wil,
             __nv_bfloat16* __restrict__ woh, __nv_bfloat16* __restrict__ wol)
{
    const int i = (blockIdx.x * 256 + threadIdx.x) * 4;
    const float* src;
    __nv_bfloat16 *hi, *lo;
    int off;
    if (i < SQ * DM)              { src = x;  hi = xh;  lo = xl;  off = i; }
    else if (i < SQ * DM + DM*DM) { src = wi; hi = wih; lo = wil; off = i - SQ * DM; }
    else                          { src = wo; hi = woh; lo = wol; off = i - SQ * DM - DM * DM; }

    float4 v = *(const float4*)(src + off);
    __nv_bfloat16 h0 = __float2bfloat16(v.x);
    __nv_bfloat16 h1 = __float2bfloat16(v.y);
    __nv_bfloat16 h2 = __float2bfloat16(v.z);
    __nv_bfloat16 h3 = __float2bfloat16(v.w);
    __nv_bfloat162 hv0; hv0.x = h0; hv0.y = h1;
    __nv_bfloat162 hv1; hv1.x = h2; hv1.y = h3;
    __nv_bfloat162 lv0, lv1;
    lv0.x = __float2bfloat16(v.x - __bfloat162float(h0));
    lv0.y = __float2bfloat16(v.y - __bfloat162float(h1));
    lv1.x = __float2bfloat16(v.z - __bfloat162float(h2));
    lv1.y = __float2bfloat16(v.w - __bfloat162float(h3));
    *(__nv_bfloat162*)(hi + off)     = hv0;
    *(__nv_bfloat162*)(hi + off + 2) = hv1;
    *(__nv_bfloat162*)(lo + off)     = lv0;
    *(__nv_bfloat162*)(lo + off + 2) = lv1;
}

// ---------------------------------------------------------------------------
// bf16x3 NT GEMM (unchanged; closed at ~53-57us: legacy-HMMA issue ceiling).
// ---------------------------------------------------------------------------
#define SROW 40
#define AELEM (128 * SROW)
#define BUFELEM (4 * AELEM)
#define GSMEM (2 * BUFELEM * 2)

__device__ __forceinline__ void cp16(uint32_t sdst, const void* gsrc) {
    asm volatile("cp.async.cg.shared.global [%0], [%1], 16;" ::
                 "r"(sdst), "l"(gsrc));
}
__device__ __forceinline__ void cp_commit() {
    asm volatile("cp.async.commit_group;");
}
__device__ __forceinline__ void mma_bf16(float* c, const uint32_t* a, const uint32_t* b) {
    asm volatile(
        "mma.sync.aligned.m16n8k16.row.col.f32.bf16.bf16.f32 "
        "{%0,%1,%2,%3}, {%4,%5,%6,%7}, {%8,%9}, {%0,%1,%2,%3};"
        : "+f"(c[0]), "+f"(c[1]), "+f"(c[2]), "+f"(c[3])
        : "r"(a[0]), "r"(a[1]), "r"(a[2]), "r"(a[3]), "r"(b[0]), "r"(b[1]));
}

template <bool EPI>
__global__ __launch_bounds__(256, 2)
void gemm_bf16x3(const __nv_bfloat16* __restrict__ Ah,
                 const __nv_bfloat16* __restrict__ Al,
                 const __nv_bfloat16* __restrict__ Bh,
                 const __nv_bfloat16* __restrict__ Bl,
                 float* __restrict__ C,
                 const float* __restrict__ bias,
                 const float* __restrict__ resid)
{
    constexpr int KD = 1024, NC = 1024, NS = 32;

    extern __shared__ __nv_bfloat16 sm[];
    uint32_t sbase;
    asm("{ .reg .u64 t; cvta.to.shared.u64 t, %1; cvt.u32.u64 %0, t; }"
        : "=r"(sbase) : "l"(sm));

    const int t    = threadIdx.x;
    const int lane = t & 31;
    const int w    = t >> 5;
    const int wm   = w >> 2;
    const int wn   = w & 3;
    const int bm   = blockIdx.y;
    const int bn   = blockIdx.x;
    const int r4   = lane >> 2;
    const int c4   = lane & 3;

    const __nv_bfloat16* gsrc[4] = {
        Ah + (size_t)(bm * 128) * KD, Al + (size_t)(bm * 128) * KD,
        Bh + (size_t)(bn * 128) * KD, Bl + (size_t)(bn * 128) * KD };

    float acc[4][4][4];
#pragma unroll
    for (int i = 0; i < 4; i++)
#pragma unroll
        for (int j = 0; j < 4; j++)
#pragma unroll
            for (int q = 0; q < 4; q++) acc[i][j][q] = 0.f;

    auto issue_stage = [&](int ks, int buf) {
        const int k0 = ks * 32;
#pragma unroll
        for (int arr = 0; arr < 4; arr++) {
            const uint32_t ab = sbase + (uint32_t)(buf * BUFELEM + arr * AELEM) * 2;
            const __nv_bfloat16* src = gsrc[arr];
#pragma unroll
            for (int i = 0; i < 2; i++) {
                const int c = t + i * 256;
                const int row = c >> 2, j = c & 3;
                cp16(ab + (uint32_t)(row * SROW + j * 8) * 2,
                     src + (size_t)row * KD + k0 + j * 8);
            }
        }
        cp_commit();
    };

    issue_stage(0, 0);

    for (int ks = 0; ks < NS; ks++) {
        const int buf = ks & 1;
        if (ks + 1 < NS) {
            issue_stage(ks + 1, buf ^ 1);
            asm volatile("cp.async.wait_group 1;");
        } else {
            asm volatile("cp.async.wait_group 0;");
        }
        __syncthreads();

        const __nv_bfloat16* sAh = sm + buf * BUFELEM;
        const __nv_bfloat16* sAl = sAh + AELEM;
        const __nv_bfloat16* sBh = sAl + AELEM;
        const __nv_bfloat16* sBl = sBh + AELEM;

#pragma unroll
        for (int kk = 0; kk < 2; kk++) {
            const int kc = kk * 16 + 2 * c4;
            uint32_t bh[4][2], bl[4][2];
#pragma unroll
            for (int nt = 0; nt < 4; nt++) {
                const int n0 = wn * 32 + nt * 8 + r4;
                bh[nt][0] = *(const uint32_t*)(sBh + n0 * SROW + kc);
                bh[nt][1] = *(const uint32_t*)(sBh + n0 * SROW + kc + 8);
                bl[nt][0] = *(const uint32_t*)(sBl + n0 * SROW + kc);
                bl[nt][1] = *(const uint32_t*)(sBl + n0 * SROW + kc + 8);
            }
#pragma unroll
            for (int mt = 0; mt < 4; mt++) {
                const int m0 = wm * 64 + mt * 16 + r4;
                uint32_t ah[4], al[4];
                ah[0] = *(const uint32_t*)(sAh + m0 * SROW + kc);
                ah[1] = *(const uint32_t*)(sAh + (m0 + 8) * SROW + kc);
                ah[2] = *(const uint32_t*)(sAh + m0 * SROW + kc + 8);
                ah[3] = *(const uint32_t*)(sAh + (m0 + 8) * SROW + kc + 8);
                al[0] = *(const uint32_t*)(sAl + m0 * SROW + kc);
                al[1] = *(const uint32_t*)(sAl + (m0 + 8) * SROW + kc);
                al[2] = *(const uint32_t*)(sAl + m0 * SROW + kc + 8);
                al[3] = *(const uint32_t*)(sAl + (m0 + 8) * SROW + kc + 8);
#pragma unroll
                for (int nt = 0; nt < 4; nt++) {
                    mma_bf16(acc[mt][nt], ah, bh[nt]);
                    mma_bf16(acc[mt][nt], ah, bl[nt]);
                    mma_bf16(acc[mt][nt], al, bh[nt]);
                }
            }
        }
        __syncthreads();
    }

#pragma unroll
    for (int mt = 0; mt < 4; mt++) {
#pragma unroll
        for (int nt = 0; nt < 4; nt++) {
            const int row0 = bm * 128 + wm * 64 + mt * 16 + r4;
            const int col  = bn * 128 + wn * 32 + nt * 8 + c4 * 2;
            float2 v0 = make_float2(acc[mt][nt][0], acc[mt][nt][1]);
            float2 v1 = make_float2(acc[mt][nt][2], acc[mt][nt][3]);
            if (EPI) {
                float2 bv = *(const float2*)(bias + col);
                float2 r0 = *(const float2*)(resid + (size_t)row0 * NC + col);
                float2 r1 = *(const float2*)(resid + (size_t)(row0 + 8) * NC + col);
                v0.x += bv.x + r0.x;  v0.y += bv.y + r0.y;
                v1.x += bv.x + r1.x;  v1.y += bv.y + r1.y;
            }
            *(float2*)(C + (size_t)row0 * NC + col)       = v0;
            *(float2*)(C + (size_t)(row0 + 8) * NC + col) = v1;
        }
    }
}

// ---------------------------------------------------------------------------
// Attention-fusion v5: gather via cp.async.cg straight to smem (no
// LDG->reg->STS roundtrip, L2-direct), rest identical to v4 best.
// Row stride 68 floats = 272B (16B multiple) keeps cp.async alignment.
// ---------------------------------------------------------------------------
#define NBS 68
__global__ __launch_bounds__(64)
void attn_kernel(const float* __restrict__ hbuf,
                 const int32_t* __restrict__ routes,
                 __nv_bfloat16* __restrict__ fh,
                 __nv_bfloat16* __restrict__ fl)
{
    const int s  = blockIdx.x;
    const int hh = blockIdx.y;
    const int t  = threadIdx.x;

    __shared__ float nb[NK][NBS];
    __shared__ float q[HDD];
    __shared__ float sc[NK];
    __shared__ float wred[4];
    __shared__ int   rt[NK];

    uint32_t nbbase;
    asm("{ .reg .u64 a; cvta.to.shared.u64 a, %1; cvt.u32.u64 %0, a; }"
        : "=r"(nbbase) : "l"(&nb[0][0]));

    rt[t] = routes[(size_t)s * NK + t] & (SQ - 1);
    q[t]  = hbuf[(size_t)s * DM + hh * HDD + t];
    __syncthreads();

    // Coalesced gather via cp.async: group g (of 4) fetches row p*4+g,
    // 16 lanes x 16B cover the 256B row slice.
    const int g = t >> 4;
    const int i4 = (t & 15) * 4;
#pragma unroll
    for (int p = 0; p < 16; p++) {
        const int k = p * 4 + g;
        cp16(nbbase + (uint32_t)(k * NBS + i4) * 4,
             hbuf + (size_t)rt[k] * DM + hh * HDD + i4);
    }
    cp_commit();
    asm volatile("cp.async.wait_group 0;" ::: "memory");
    __syncthreads();

    // Scores: thread t = neighbor t
    float dot = 0.f;
#pragma unroll
    for (int d0 = 0; d0 < HDD; d0 += 4) {
        float4 v  = *(const float4*)&nb[t][d0];
        float4 qv = *(const float4*)&q[d0];
        dot = fmaf(v.x, qv.x, dot);
        dot = fmaf(v.y, qv.y, dot);
        dot = fmaf(v.z, qv.z, dot);
        dot = fmaf(v.w, qv.w, dot);
    }
    const float st = dot * 0.125f;

    float m = st;
    m = fmaxf(m, __shfl_xor_sync(0xFFFFFFFF, m, 16));
    m = fmaxf(m, __shfl_xor_sync(0xFFFFFFFF, m, 8));
    m = fmaxf(m, __shfl_xor_sync(0xFFFFFFFF, m, 4));
    m = fmaxf(m, __shfl_xor_sync(0xFFFFFFFF, m, 2));
    m = fmaxf(m, __shfl_xor_sync(0xFFFFFFFF, m, 1));
    if ((t & 31) == 0) wred[t >> 5] = m;
    __syncthreads();
    const float mx = fmaxf(wred[0], wred[1]);

    const float wexp = __expf(st - mx);
    sc[t] = wexp;

    float ss = wexp;
    ss += __shfl_xor_sync(0xFFFFFFFF, ss, 16);
    ss += __shfl_xor_sync(0xFFFFFFFF, ss, 8);
    ss += __shfl_xor_sync(0xFFFFFFFF, ss, 4);
    ss += __shfl_xor_sync(0xFFFFFFFF, ss, 2);
    ss += __shfl_xor_sync(0xFFFFFFFF, ss, 1);
    if ((t & 31) == 0) wred[2 + (t >> 5)] = ss;
    __syncthreads();
    const float sum = wred[2] + wred[3];

    float accv = 0.f;
#pragma unroll
    for (int k4 = 0; k4 < 16; k4++) {
        const float4 ws = *(const float4*)&sc[k4 * 4];
        accv = fmaf(ws.x, nb[k4 * 4 + 0][t], accv);
        accv = fmaf(ws.y, nb[k4 * 4 + 1][t], accv);
        accv = fmaf(ws.z, nb[k4 * 4 + 2][t], accv);
        accv = fmaf(ws.w, nb[k4 * 4 + 3][t], accv);
    }
    const float val = accv / sum;
    const size_t idx = (size_t)s * DM + hh * HDD + t;
    __nv_bfloat16 hv = __float2bfloat16(val);
    fh[idx] = hv;
    fl[idx] = __float2bfloat16(val - __bfloat162float(hv));
}

// ---------------------------------------------------------------------------
// Launch
// ---------------------------------------------------------------------------
extern "C" void kernel_launch(void* const* d_in, const int* in_sizes, int n_in,
                              void* d_out, int out_size)
{
    const float*   x      = nullptr;
    const int32_t* routes = nullptr;
    const float*   W_in   = nullptr;
    const float*   W_out  = nullptr;
    const float*   b_out  = nullptr;

    for (int i = 0; i < n_in; i++) {
        const int sz = in_sizes[i];
        if      (sz == SQ * DM)  { x = (const float*)d_in[i]; }
        else if (sz == SQ * NK)  { routes = (const int32_t*)d_in[i]; }
        else if (sz == DM * DM)  { if (!W_in) W_in = (const float*)d_in[i];
                                   else       W_out = (const float*)d_in[i]; }
        else if (sz == DM)       { b_out = (const float*)d_in[i]; }
    }
    float* out = (float*)d_out;

    float *hbuf;
    __nv_bfloat16 *xh, *xl, *wih, *wil, *woh, *wol, *fh, *fl;
    cudaGetSymbolAddress((void**)&hbuf, g_h);
    cudaGetSymbolAddress((void**)&xh,  g_xh);  cudaGetSymbolAddress((void**)&xl,  g_xl);
    cudaGetSymbolAddress((void**)&wih, g_wih); cudaGetSymbolAddress((void**)&wil, g_wil);
    cudaGetSymbolAddress((void**)&woh, g_woh); cudaGetSymbolAddress((void**)&wol, g_wol);
    cudaGetSymbolAddress((void**)&fh,  g_fh);  cudaGetSymbolAddress((void**)&fl,  g_fl);

    cudaFuncSetAttribute(gemm_bf16x3<false>,
                         cudaFuncAttributeMaxDynamicSharedMemorySize, GSMEM);
    cudaFuncSetAttribute(gemm_bf16x3<true>,
                         cudaFuncAttributeMaxDynamicSharedMemorySize, GSMEM);

    cvt_all<<<(SQ * DM + 2 * DM * DM) / 1024, 256>>>(x, W_in, W_out,
                                                     xh, xl, wih, wil, woh, wol);

    dim3 gGemm(DM / 128, SQ / 128);   // (8, 16)

    gemm_bf16x3<false><<<gGemm, 256, GSMEM>>>(xh, xl, wih, wil, hbuf,
                                              nullptr, nullptr);
    attn_kernel<<<dim3(SQ, NH), 64>>>(hbuf, routes, fh, fl);
    gemm_bf16x3<true><<<gGemm, 256, GSMEM>>>(fh, fl, woh, wol, out, b_out, x);
}